// round 1
// baseline (speedup 1.0000x reference)
#include <cuda_runtime.h>
#include <math.h>

#define NN 4096
#define CC 256
#define HH 8
#define DHH 32
#define LL 3
#define EPSV 1e-5f
#define ATT_SCALE 0.17677669529663687f   // 1/sqrt(32)

// ---------------- scratch (no allocation allowed) ----------------
__device__ float g_h[NN*CC];
__device__ float g_agg[NN*CC];
__device__ float g_t1[NN*2*CC];
__device__ float g_t2[NN*CC];
__device__ float g_q[NN*CC];
__device__ float g_k[NN*CC];
__device__ float g_v[NN*CC];
__device__ float g_o[NN*CC];
__device__ float g_h1[NN*CC];
__device__ float g_sum[CC];
__device__ float g_sumsq[CC];

// ---------------- small kernels ----------------
__global__ void lin1_kernel(const float* __restrict__ x, const float* __restrict__ w,
                            const float* __restrict__ b) {
    int n = blockIdx.x, c = threadIdx.x;
    g_h[n*CC + c] = x[n]*w[c] + b[c];
}

__global__ void zero_kernel(float* __restrict__ p, int n) {
    int i = blockIdx.x*blockDim.x + threadIdx.x;
    if (i < n) p[i] = 0.f;
}

__global__ void zero_stats_kernel() {
    g_sum[threadIdx.x]   = 0.f;
    g_sumsq[threadIdx.x] = 0.f;
}

// agg[dst] += h[src], per edge, 256 channels per edge
__global__ void scatter_kernel(const int* __restrict__ ei, int E) {
    const int* src = ei;
    const int* dst = ei + E;
    int c = threadIdx.x;
    int e0 = blockIdx.x * 4;
    #pragma unroll
    for (int k = 0; k < 4; k++) {
        int e = e0 + k;
        int s = src[e], d = dst[e];
        atomicAdd(&g_agg[d*CC + c], g_h[s*CC + c]);
    }
}

// BN stats over node dim: v = in1 + in2, accumulate sum/sumsq per channel
__global__ void bn_stats_kernel(const float* __restrict__ in1, const float* __restrict__ in2) {
    int c = threadIdx.x;
    int r0 = blockIdx.x * 128;
    float s = 0.f, ss = 0.f;
    for (int r = r0; r < r0 + 128; r++) {
        float v = in1[r*CC + c] + in2[r*CC + c];
        s += v; ss += v*v;
    }
    atomicAdd(&g_sum[c], s);
    atomicAdd(&g_sumsq[c], ss);
}

// out = BN(in1+in2)*g + b  (+ addend), biased variance
__global__ void bn_apply_kernel(const float* __restrict__ in1, const float* __restrict__ in2,
                                const float* __restrict__ gamma, const float* __restrict__ beta,
                                const float* __restrict__ addend, float* __restrict__ out) {
    int i = blockIdx.x*256 + threadIdx.x;
    int c = i & (CC-1);
    float mean = g_sum[c] * (1.f/NN);
    float var  = g_sumsq[c] * (1.f/NN) - mean*mean;
    float v = in1[i] + in2[i];
    float r = (v - mean) * rsqrtf(var + EPSV) * gamma[c] + beta[c];
    if (addend) r += addend[i];
    out[i] = r;
}

// ---------------- GEMM: C[M,Nout] = act((A1(+A2)) @ B^T + bias) ----------------
// A row-major [M,K], B row-major [Nout,K] (torch Linear weight layout)
__global__ void __launch_bounds__(256) gemm_kernel(
    const float* __restrict__ A1, const float* __restrict__ A2,
    const float* __restrict__ B, const float* __restrict__ bias,
    float* __restrict__ C, int M, int Nout, int K, int relu)
{
    __shared__ float As[32][68];
    __shared__ float Bs[32][68];
    int tid = threadIdx.x;
    int tx = tid & 15, ty = tid >> 4;
    int m0 = blockIdx.y * 64, n0 = blockIdx.x * 64;
    float acc[4][4] = {};
    for (int k0 = 0; k0 < K; k0 += 32) {
        #pragma unroll
        for (int i = 0; i < 8; i++) {
            int idx = i*256 + tid;
            int r = idx >> 5, kk = idx & 31;
            float a = A1[(m0+r)*K + k0 + kk];
            if (A2) a += A2[(m0+r)*K + k0 + kk];
            As[kk][r] = a;
            Bs[kk][r] = B[(n0+r)*K + k0 + kk];
        }
        __syncthreads();
        #pragma unroll
        for (int kk = 0; kk < 32; kk++) {
            float4 a4 = *(const float4*)&As[kk][ty*4];
            float4 b4 = *(const float4*)&Bs[kk][tx*4];
            acc[0][0] += a4.x*b4.x; acc[0][1] += a4.x*b4.y; acc[0][2] += a4.x*b4.z; acc[0][3] += a4.x*b4.w;
            acc[1][0] += a4.y*b4.x; acc[1][1] += a4.y*b4.y; acc[1][2] += a4.y*b4.z; acc[1][3] += a4.y*b4.w;
            acc[2][0] += a4.z*b4.x; acc[2][1] += a4.z*b4.y; acc[2][2] += a4.z*b4.z; acc[2][3] += a4.z*b4.w;
            acc[3][0] += a4.w*b4.x; acc[3][1] += a4.w*b4.y; acc[3][2] += a4.w*b4.z; acc[3][3] += a4.w*b4.w;
        }
        __syncthreads();
    }
    #pragma unroll
    for (int i = 0; i < 4; i++) {
        int m = m0 + ty*4 + i;
        #pragma unroll
        for (int j = 0; j < 4; j++) {
            int n = n0 + tx*4 + j;
            float v = acc[i][j] + bias[n];
            if (relu) v = fmaxf(v, 0.f);
            C[m*Nout + n] = v;
        }
    }
}

// ---------------- flash attention (fp32, per (head, 64-row q-tile)) ----------------
__global__ void __launch_bounds__(256) flash_kernel(
    const float* __restrict__ Q, const float* __restrict__ Kp,
    const float* __restrict__ V, float* __restrict__ O)
{
    __shared__ float Qs[32][68];
    __shared__ float Ks[32][68];
    __shared__ float Ps[64][68];
    __shared__ float Vs[64][36];
    int tid = threadIdx.x;
    int tx = tid & 15, ty = tid >> 4;
    int hoff = blockIdx.y * DHH;
    int q0 = blockIdx.x * 64;

    #pragma unroll
    for (int i = 0; i < 8; i++) {
        int idx = i*256 + tid;
        int r = idx >> 5, d = idx & 31;
        Qs[d][r] = Q[(q0+r)*CC + hoff + d] * ATT_SCALE;
    }
    float mrow[4], lrow[4], acc[4][2];
    #pragma unroll
    for (int i = 0; i < 4; i++) { mrow[i] = -1e30f; lrow[i] = 0.f; acc[i][0] = 0.f; acc[i][1] = 0.f; }
    __syncthreads();

    for (int j0 = 0; j0 < NN; j0 += 64) {
        #pragma unroll
        for (int i = 0; i < 8; i++) {
            int idx = i*256 + tid;
            int r = idx >> 5, d = idx & 31;
            Ks[d][r] = Kp[(j0+r)*CC + hoff + d];
            Vs[r][d] = V [(j0+r)*CC + hoff + d];
        }
        __syncthreads();

        float s[4][4] = {};
        #pragma unroll
        for (int d = 0; d < 32; d++) {
            float4 a4 = *(const float4*)&Qs[d][ty*4];
            float4 b4 = *(const float4*)&Ks[d][tx*4];
            s[0][0] += a4.x*b4.x; s[0][1] += a4.x*b4.y; s[0][2] += a4.x*b4.z; s[0][3] += a4.x*b4.w;
            s[1][0] += a4.y*b4.x; s[1][1] += a4.y*b4.y; s[1][2] += a4.y*b4.z; s[1][3] += a4.y*b4.w;
            s[2][0] += a4.z*b4.x; s[2][1] += a4.z*b4.y; s[2][2] += a4.z*b4.z; s[2][3] += a4.z*b4.w;
            s[3][0] += a4.w*b4.x; s[3][1] += a4.w*b4.y; s[3][2] += a4.w*b4.z; s[3][3] += a4.w*b4.w;
        }
        // online softmax per row (row-group = 16 lanes with same ty, contiguous in warp)
        #pragma unroll
        for (int i = 0; i < 4; i++) {
            float rm = fmaxf(fmaxf(s[i][0], s[i][1]), fmaxf(s[i][2], s[i][3]));
            #pragma unroll
            for (int o = 8; o >= 1; o >>= 1) rm = fmaxf(rm, __shfl_xor_sync(0xffffffffu, rm, o));
            float mnew = fmaxf(mrow[i], rm);
            float rs = 0.f;
            #pragma unroll
            for (int j = 0; j < 4; j++) { s[i][j] = __expf(s[i][j] - mnew); rs += s[i][j]; }
            #pragma unroll
            for (int o = 8; o >= 1; o >>= 1) rs += __shfl_xor_sync(0xffffffffu, rs, o);
            float cf = __expf(mrow[i] - mnew);
            lrow[i] = lrow[i]*cf + rs;
            mrow[i] = mnew;
            acc[i][0] *= cf; acc[i][1] *= cf;
            #pragma unroll
            for (int j = 0; j < 4; j++) Ps[tx*4+j][ty*4+i] = s[i][j];
        }
        __syncthreads();

        // O += P @ V  (64x64 * 64x32), thread owns rows ty*4+i, dims tx*2+d
        #pragma unroll 8
        for (int j = 0; j < 64; j++) {
            float4 p4 = *(const float4*)&Ps[j][ty*4];
            float2 vv = *(const float2*)&Vs[j][tx*2];
            acc[0][0] += p4.x*vv.x; acc[0][1] += p4.x*vv.y;
            acc[1][0] += p4.y*vv.x; acc[1][1] += p4.y*vv.y;
            acc[2][0] += p4.z*vv.x; acc[2][1] += p4.z*vv.y;
            acc[3][0] += p4.w*vv.x; acc[3][1] += p4.w*vv.y;
        }
        __syncthreads();
    }
    #pragma unroll
    for (int i = 0; i < 4; i++) {
        float inv = 1.f / lrow[i];
        int r = q0 + ty*4 + i;
        O[r*CC + hoff + tx*2 + 0] = acc[i][0]*inv;
        O[r*CC + hoff + tx*2 + 1] = acc[i][1]*inv;
    }
}

// ---------------- host ----------------
extern "C" void kernel_launch(void* const* d_in, const int* in_sizes, int n_in,
                              void* d_out, int out_size) {
    const float* x      = (const float*)d_in[0];
    const int*   ei     = (const int*)  d_in[1];
    const float* lin1_w = (const float*)d_in[2];
    const float* lin1_b = (const float*)d_in[3];
    const float* gin_w1 = (const float*)d_in[4];
    const float* gin_b1 = (const float*)d_in[5];
    const float* gin_w2 = (const float*)d_in[6];
    const float* gin_b2 = (const float*)d_in[7];
    const float* wq = (const float*)d_in[8];
    const float* wk = (const float*)d_in[9];
    const float* wv = (const float*)d_in[10];
    const float* wo = (const float*)d_in[11];
    const float* bq = (const float*)d_in[12];
    const float* bk = (const float*)d_in[13];
    const float* bv = (const float*)d_in[14];
    const float* bo = (const float*)d_in[15];
    const float* bn1_g = (const float*)d_in[16];
    const float* bn1_b = (const float*)d_in[17];
    const float* bn2_g = (const float*)d_in[18];
    const float* bn2_b = (const float*)d_in[19];
    const float* bn3_g = (const float*)d_in[20];
    const float* bn3_b = (const float*)d_in[21];
    const float* mw1 = (const float*)d_in[22];
    const float* mb1 = (const float*)d_in[23];
    const float* mw2 = (const float*)d_in[24];
    const float* mb2 = (const float*)d_in[25];
    int E = in_sizes[1] / 2;

    float *h, *agg, *t1, *t2, *q, *k, *v, *o, *h1;
    cudaGetSymbolAddress((void**)&h,   g_h);
    cudaGetSymbolAddress((void**)&agg, g_agg);
    cudaGetSymbolAddress((void**)&t1,  g_t1);
    cudaGetSymbolAddress((void**)&t2,  g_t2);
    cudaGetSymbolAddress((void**)&q,   g_q);
    cudaGetSymbolAddress((void**)&k,   g_k);
    cudaGetSymbolAddress((void**)&v,   g_v);
    cudaGetSymbolAddress((void**)&o,   g_o);
    cudaGetSymbolAddress((void**)&h1,  g_h1);

    dim3 g64 (CC/64,   NN/64);   // 4 x 64 blocks
    dim3 g64w(2*CC/64, NN/64);   // 8 x 64 blocks
    int ewgrid = NN*CC/256;

    lin1_kernel<<<NN, CC>>>(x, lin1_w, lin1_b);

    for (int l = 0; l < LL; l++) {
        // ---- GIN branch ----
        zero_kernel<<<ewgrid, 256>>>(agg, NN*CC);
        scatter_kernel<<<E/4, CC>>>(ei, E);
        gemm_kernel<<<g64, 256>>>(h, agg, gin_w1 + l*CC*CC, gin_b1 + l*CC, t1, NN, CC, CC, 1);
        gemm_kernel<<<g64, 256>>>(t1, nullptr, gin_w2 + l*CC*CC, gin_b2 + l*CC, t2, NN, CC, CC, 0);
        zero_stats_kernel<<<1, CC>>>();
        bn_stats_kernel<<<32, CC>>>(t2, h);
        bn_apply_kernel<<<ewgrid, 256>>>(t2, h, bn1_g + l*CC, bn1_b + l*CC, nullptr, h1);
        // ---- global attention ----
        gemm_kernel<<<g64, 256>>>(h, nullptr, wq + l*CC*CC, bq + l*CC, q, NN, CC, CC, 0);
        gemm_kernel<<<g64, 256>>>(h, nullptr, wk + l*CC*CC, bk + l*CC, k, NN, CC, CC, 0);
        gemm_kernel<<<g64, 256>>>(h, nullptr, wv + l*CC*CC, bv + l*CC, v, NN, CC, CC, 0);
        flash_kernel<<<dim3(NN/64, HH), 256>>>(q, k, v, o);
        gemm_kernel<<<g64, 256>>>(o, nullptr, wo + l*CC*CC, bo + l*CC, t2, NN, CC, CC, 0);
        zero_stats_kernel<<<1, CC>>>();
        bn_stats_kernel<<<32, CC>>>(t2, h);
        // s = h1 + h2 written into q (q no longer needed)
        bn_apply_kernel<<<ewgrid, 256>>>(t2, h, bn2_g + l*CC, bn2_b + l*CC, h1, q);
        // ---- feedforward ----
        gemm_kernel<<<g64w, 256>>>(q, nullptr, mw1 + l*2*CC*CC, mb1 + l*2*CC, t1, NN, 2*CC, CC, 1);
        gemm_kernel<<<g64, 256>>>(t1, nullptr, mw2 + l*2*CC*CC, mb2 + l*CC, t2, NN, CC, 2*CC, 0);
        zero_stats_kernel<<<1, CC>>>();
        bn_stats_kernel<<<32, CC>>>(t2, q);
        bn_apply_kernel<<<ewgrid, 256>>>(t2, q, bn3_g + l*CC, bn3_b + l*CC, nullptr,
                                         (l == LL-1) ? (float*)d_out : h);
    }
    (void)n_in; (void)out_size;
}

// round 7
// speedup vs baseline: 2.4008x; 2.4008x over previous
#include <cuda_runtime.h>
#include <cuda_fp16.h>
#include <math.h>
#include <stdint.h>

#define NN 4096
#define CC 256
#define HH 8
#define DHH 32
#define LL 3
#define EPSV 1e-5f
// 1/sqrt(32) * log2(e): fold attention scale + exp->exp2 conversion into Q
#define QSC (0.17677669529663687f * 1.4426950408889634f)

// ---------------- scratch (no allocation allowed) ----------------
__device__ float g_h[NN*CC];
__device__ float g_agg[NN*CC];
__device__ float g_t1[NN*2*CC];
__device__ float g_t2[NN*CC];
__device__ float g_q[NN*CC];
__device__ float g_k[NN*CC];
__device__ float g_v[NN*CC];
__device__ float g_o[NN*CC];
__device__ float g_h1[NN*CC];
__device__ float g_sum[CC];
__device__ float g_sumsq[CC];

// ---------------- warp mma helper (sm_80+ HMMA fp16, no arch-a features) ----------------
__device__ __forceinline__ void mma16816(float* d, const uint32_t* a, const uint32_t* b) {
    asm volatile(
        "mma.sync.aligned.m16n8k16.row.col.f32.f16.f16.f32 "
        "{%0,%1,%2,%3}, {%4,%5,%6,%7}, {%8,%9}, {%0,%1,%2,%3};"
        : "+f"(d[0]), "+f"(d[1]), "+f"(d[2]), "+f"(d[3])
        : "r"(a[0]), "r"(a[1]), "r"(a[2]), "r"(a[3]), "r"(b[0]), "r"(b[1]));
}

__device__ __forceinline__ uint32_t packh2(float x, float y) {
    __half2 h = __floats2half2_rn(x, y);
    return *(uint32_t*)&h;
}

// ---------------- flash attention via mma.sync (fp16 in, fp32 accum) ----------------
// grid (NN/128, HH), 128 threads (4 warps). FA2 online softmax (running row max),
// so P = 2^(s-m) <= 1 always fits fp16.
#define QPAD 36
#define VPAD 132
__global__ void __launch_bounds__(128) flash_mma_kernel(
    const float* __restrict__ Q, const float* __restrict__ Kp,
    const float* __restrict__ V, float* __restrict__ Og)
{
    __shared__ __half Qs[128][QPAD];
    __shared__ __half Ks[128][QPAD];
    __shared__ __half VTs[32][VPAD];

    const int tid = threadIdx.x;
    const int w = tid >> 5, lane = tid & 31;
    const int g = lane >> 2, tc = lane & 3;
    const int hoff = blockIdx.y * DHH;
    const int q0 = blockIdx.x * 128;

    // stage Q tile [128 x 32] fp16 (scaled), padded rows
    #pragma unroll
    for (int it = 0; it < 16; it++) {
        int idx = it*128 + tid;
        int r = idx >> 4, pr = idx & 15;
        float2 f = *(const float2*)&Q[(q0 + r)*CC + hoff + pr*2];
        *(__half2*)&Qs[r][pr*2] = __floats2half2_rn(f.x * QSC, f.y * QSC);
    }
    __syncthreads();

    // Q A-fragments: 2 m16 tiles x 2 k16 tiles, resident in registers
    uint32_t qa[2][2][4];
    #pragma unroll
    for (int mt = 0; mt < 2; mt++) {
        #pragma unroll
        for (int kt = 0; kt < 2; kt++) {
            int r0 = w*32 + mt*16 + g;
            qa[mt][kt][0] = *(const uint32_t*)&Qs[r0    ][kt*16 + 2*tc    ];
            qa[mt][kt][1] = *(const uint32_t*)&Qs[r0 + 8][kt*16 + 2*tc    ];
            qa[mt][kt][2] = *(const uint32_t*)&Qs[r0    ][kt*16 + 2*tc + 8];
            qa[mt][kt][3] = *(const uint32_t*)&Qs[r0 + 8][kt*16 + 2*tc + 8];
        }
    }

    float oacc[2][4][4] = {};
    float lacc[4] = {};                          // [mt*2 + hi]
    float mrow[4] = {-1e30f, -1e30f, -1e30f, -1e30f};

    for (int j0 = 0; j0 < NN; j0 += 128) {
        __syncthreads();   // previous block's K/V reads complete before overwrite
        // K tile [128 keys x 32 dims] fp16
        #pragma unroll
        for (int it = 0; it < 16; it++) {
            int idx = it*128 + tid;
            int r = idx >> 4, pr = idx & 15;
            float2 f = *(const float2*)&Kp[(j0 + r)*CC + hoff + pr*2];
            *(__half2*)&Ks[r][pr*2] = __floats2half2_rn(f.x, f.y);
        }
        // V^T tile [32 dims x 128 keys] fp16
        #pragma unroll
        for (int it = 0; it < 16; it++) {
            int idx = it*128 + tid;
            int j = idx >> 4, dp = idx & 15;
            float2 f = *(const float2*)&V[(j0 + j)*CC + hoff + dp*2];
            VTs[dp*2    ][j] = __float2half(f.x);
            VTs[dp*2 + 1][j] = __float2half(f.y);
        }
        __syncthreads();

        // process 16-key groups
        #pragma unroll
        for (int ng = 0; ng < 8; ng++) {
            const int kb = ng*16;
            float s[2][2][4] = {};
            // S = Q . K^T over k-dim 32 (2 k16 steps)
            #pragma unroll
            for (int kt = 0; kt < 2; kt++) {
                uint32_t b[2][2];
                #pragma unroll
                for (int j = 0; j < 2; j++) {
                    int key = kb + j*8 + g;
                    b[j][0] = *(const uint32_t*)&Ks[key][kt*16 + 2*tc    ];
                    b[j][1] = *(const uint32_t*)&Ks[key][kt*16 + 2*tc + 8];
                }
                #pragma unroll
                for (int mt = 0; mt < 2; mt++)
                    #pragma unroll
                    for (int j = 0; j < 2; j++)
                        mma16816(s[mt][j], qa[mt][kt], b[j]);
            }
            // online softmax: per row (mt, hi) running max + rescale.
            // S d-frag {d0..d3} of n8-tile j: rows (g,g,g+8,g+8), keys (kb+j*8+2tc,+1).
            // P A-frag order: a0=j0 row g, a1=j0 row g+8, a2=j1 row g, a3=j1 row g+8.
            uint32_t pa[2][4];
            #pragma unroll
            for (int mt = 0; mt < 2; mt++) {
                #pragma unroll
                for (int hi = 0; hi < 2; hi++) {
                    float rm = fmaxf(fmaxf(s[mt][0][2*hi], s[mt][0][2*hi+1]),
                                     fmaxf(s[mt][1][2*hi], s[mt][1][2*hi+1]));
                    rm = fmaxf(rm, __shfl_xor_sync(0xffffffffu, rm, 1));
                    rm = fmaxf(rm, __shfl_xor_sync(0xffffffffu, rm, 2));
                    float mold = mrow[mt*2 + hi];
                    float mnew = fmaxf(mold, rm);
                    float cf = exp2f(mold - mnew);      // quad-uniform
                    mrow[mt*2 + hi] = mnew;
                    float p00 = exp2f(s[mt][0][2*hi]   - mnew);
                    float p01 = exp2f(s[mt][0][2*hi+1] - mnew);
                    float p10 = exp2f(s[mt][1][2*hi]   - mnew);
                    float p11 = exp2f(s[mt][1][2*hi+1] - mnew);
                    lacc[mt*2 + hi] = lacc[mt*2 + hi]*cf + p00 + p01 + p10 + p11;
                    pa[mt][0*2 + hi] = packh2(p00, p01);
                    pa[mt][1*2 + hi] = packh2(p10, p11);
                    #pragma unroll
                    for (int dj = 0; dj < 4; dj++) {
                        oacc[mt][dj][2*hi]   *= cf;
                        oacc[mt][dj][2*hi+1] *= cf;
                    }
                }
            }
            // O += P . V  (n = 32 dims -> 4 n8 tiles)
            #pragma unroll
            for (int dj = 0; dj < 4; dj++) {
                uint32_t vb[2];
                vb[0] = *(const uint32_t*)&VTs[dj*8 + g][kb + 2*tc    ];
                vb[1] = *(const uint32_t*)&VTs[dj*8 + g][kb + 2*tc + 8];
                #pragma unroll
                for (int mt = 0; mt < 2; mt++)
                    mma16816(oacc[mt][dj], pa[mt], vb);
            }
        }
    }

    // reduce l across the 4-thread row group (m already quad-uniform)
    #pragma unroll
    for (int i = 0; i < 4; i++) {
        lacc[i] += __shfl_xor_sync(0xffffffffu, lacc[i], 1);
        lacc[i] += __shfl_xor_sync(0xffffffffu, lacc[i], 2);
    }
    // write O
    #pragma unroll
    for (int mt = 0; mt < 2; mt++) {
        int rbase = q0 + w*32 + mt*16;
        float inv0 = 1.f / lacc[mt*2 + 0];
        float inv1 = 1.f / lacc[mt*2 + 1];
        #pragma unroll
        for (int dj = 0; dj < 4; dj++) {
            int col = hoff + dj*8 + 2*tc;
            *(float2*)&Og[(rbase + g    )*CC + col] =
                make_float2(oacc[mt][dj][0]*inv0, oacc[mt][dj][1]*inv0);
            *(float2*)&Og[(rbase + g + 8)*CC + col] =
                make_float2(oacc[mt][dj][2]*inv1, oacc[mt][dj][3]*inv1);
        }
    }
}

// ---------------- small kernels ----------------
__global__ void lin1_kernel(const float* __restrict__ x, const float* __restrict__ w,
                            const float* __restrict__ b) {
    int n = blockIdx.x, c = threadIdx.x;
    g_h[n*CC + c] = x[n]*w[c] + b[c];
}

__global__ void zero_kernel(float* __restrict__ p, int n) {
    int i = blockIdx.x*blockDim.x + threadIdx.x;
    if (i < n) p[i] = 0.f;
}

__global__ void zero_stats_kernel() {
    g_sum[threadIdx.x]   = 0.f;
    g_sumsq[threadIdx.x] = 0.f;
}

__global__ void scatter_kernel(const int* __restrict__ ei, int E) {
    const int* src = ei;
    const int* dst = ei + E;
    int c = threadIdx.x;
    int e0 = blockIdx.x * 4;
    #pragma unroll
    for (int k = 0; k < 4; k++) {
        int e = e0 + k;
        int s = src[e], d = dst[e];
        atomicAdd(&g_agg[d*CC + c], g_h[s*CC + c]);
    }
}

__global__ void bn_stats_kernel(const float* __restrict__ in1, const float* __restrict__ in2) {
    int c = threadIdx.x;
    int r0 = blockIdx.x * 128;
    float s = 0.f, ss = 0.f;
    for (int r = r0; r < r0 + 128; r++) {
        float v = in1[r*CC + c] + in2[r*CC + c];
        s += v; ss += v*v;
    }
    atomicAdd(&g_sum[c], s);
    atomicAdd(&g_sumsq[c], ss);
}

__global__ void bn_apply_kernel(const float* __restrict__ in1, const float* __restrict__ in2,
                                const float* __restrict__ gamma, const float* __restrict__ beta,
                                const float* __restrict__ addend, float* __restrict__ out) {
    int i = blockIdx.x*256 + threadIdx.x;
    int c = i & (CC-1);
    float mean = g_sum[c] * (1.f/NN);
    float var  = g_sumsq[c] * (1.f/NN) - mean*mean;
    float v = in1[i] + in2[i];
    float r = (v - mean) * rsqrtf(var + EPSV) * gamma[c] + beta[c];
    if (addend) r += addend[i];
    out[i] = r;
}

// ---------------- fp32 SIMT GEMM body ----------------
__device__ __forceinline__ void gemm_body(
    const float* __restrict__ A1, const float* __restrict__ A2,
    const float* __restrict__ B, const float* __restrict__ bias,
    float* __restrict__ C, int M, int Nout, int K, int relu)
{
    __shared__ float As[32][68];
    __shared__ float Bs[32][68];
    int tid = threadIdx.x;
    int tx = tid & 15, ty = tid >> 4;
    int m0 = blockIdx.y * 64, n0 = blockIdx.x * 64;
    float acc[4][4] = {};
    for (int k0 = 0; k0 < K; k0 += 32) {
        #pragma unroll
        for (int i = 0; i < 8; i++) {
            int idx = i*256 + tid;
            int r = idx >> 5, kk = idx & 31;
            float a = A1[(m0+r)*K + k0 + kk];
            if (A2) a += A2[(m0+r)*K + k0 + kk];
            As[kk][r] = a;
            Bs[kk][r] = B[(n0+r)*K + k0 + kk];
        }
        __syncthreads();
        #pragma unroll
        for (int kk = 0; kk < 32; kk++) {
            float4 a4 = *(const float4*)&As[kk][ty*4];
            float4 b4 = *(const float4*)&Bs[kk][tx*4];
            acc[0][0] += a4.x*b4.x; acc[0][1] += a4.x*b4.y; acc[0][2] += a4.x*b4.z; acc[0][3] += a4.x*b4.w;
            acc[1][0] += a4.y*b4.x; acc[1][1] += a4.y*b4.y; acc[1][2] += a4.y*b4.z; acc[1][3] += a4.y*b4.w;
            acc[2][0] += a4.z*b4.x; acc[2][1] += a4.z*b4.y; acc[2][2] += a4.z*b4.z; acc[2][3] += a4.z*b4.w;
            acc[3][0] += a4.w*b4.x; acc[3][1] += a4.w*b4.y; acc[3][2] += a4.w*b4.z; acc[3][3] += a4.w*b4.w;
        }
        __syncthreads();
    }
    #pragma unroll
    for (int i = 0; i < 4; i++) {
        int m = m0 + ty*4 + i;
        #pragma unroll
        for (int j = 0; j < 4; j++) {
            int n = n0 + tx*4 + j;
            float v = acc[i][j] + bias[n];
            if (relu) v = fmaxf(v, 0.f);
            C[m*Nout + n] = v;
        }
    }
}

__global__ void __launch_bounds__(256) gemm_kernel(
    const float* __restrict__ A1, const float* __restrict__ A2,
    const float* __restrict__ B, const float* __restrict__ bias,
    float* __restrict__ C, int M, int Nout, int K, int relu)
{
    gemm_body(A1, A2, B, bias, C, M, Nout, K, relu);
}

// fused Q/K/V projection: blockIdx.z selects weight/bias/output
__global__ void __launch_bounds__(256) qkv_gemm_kernel(
    const float* __restrict__ A,
    const float* __restrict__ wq, const float* __restrict__ wk, const float* __restrict__ wv,
    const float* __restrict__ bq, const float* __restrict__ bk, const float* __restrict__ bv,
    float* __restrict__ q, float* __restrict__ k, float* __restrict__ v)
{
    const float* B; const float* bias; float* C;
    if (blockIdx.z == 0)      { B = wq; bias = bq; C = q; }
    else if (blockIdx.z == 1) { B = wk; bias = bk; C = k; }
    else                      { B = wv; bias = bv; C = v; }
    gemm_body(A, nullptr, B, bias, C, NN, CC, CC, 0);
}

// ---------------- host ----------------
extern "C" void kernel_launch(void* const* d_in, const int* in_sizes, int n_in,
                              void* d_out, int out_size) {
    const float* x      = (const float*)d_in[0];
    const int*   ei     = (const int*)  d_in[1];
    const float* lin1_w = (const float*)d_in[2];
    const float* lin1_b = (const float*)d_in[3];
    const float* gin_w1 = (const float*)d_in[4];
    const float* gin_b1 = (const float*)d_in[5];
    const float* gin_w2 = (const float*)d_in[6];
    const float* gin_b2 = (const float*)d_in[7];
    const float* wq = (const float*)d_in[8];
    const float* wk = (const float*)d_in[9];
    const float* wv = (const float*)d_in[10];
    const float* wo = (const float*)d_in[11];
    const float* bq = (const float*)d_in[12];
    const float* bk = (const float*)d_in[13];
    const float* bv = (const float*)d_in[14];
    const float* bo = (const float*)d_in[15];
    const float* bn1_g = (const float*)d_in[16];
    const float* bn1_b = (const float*)d_in[17];
    const float* bn2_g = (const float*)d_in[18];
    const float* bn2_b = (const float*)d_in[19];
    const float* bn3_g = (const float*)d_in[20];
    const float* bn3_b = (const float*)d_in[21];
    const float* mw1 = (const float*)d_in[22];
    const float* mb1 = (const float*)d_in[23];
    const float* mw2 = (const float*)d_in[24];
    const float* mb2 = (const float*)d_in[25];
    int E = in_sizes[1] / 2;

    float *h, *agg, *t1, *t2, *q, *k, *v, *o, *h1;
    cudaGetSymbolAddress((void**)&h,   g_h);
    cudaGetSymbolAddress((void**)&agg, g_agg);
    cudaGetSymbolAddress((void**)&t1,  g_t1);
    cudaGetSymbolAddress((void**)&t2,  g_t2);
    cudaGetSymbolAddress((void**)&q,   g_q);
    cudaGetSymbolAddress((void**)&k,   g_k);
    cudaGetSymbolAddress((void**)&v,   g_v);
    cudaGetSymbolAddress((void**)&o,   g_o);
    cudaGetSymbolAddress((void**)&h1,  g_h1);

    dim3 g64 (CC/64,   NN/64);
    dim3 g64w(2*CC/64, NN/64);
    dim3 gqkv(CC/64,   NN/64, 3);
    int ewgrid = NN*CC/256;

    lin1_kernel<<<NN, CC>>>(x, lin1_w, lin1_b);

    for (int l = 0; l < LL; l++) {
        // ---- GIN branch ----
        zero_kernel<<<ewgrid, 256>>>(agg, NN*CC);
        scatter_kernel<<<E/4, CC>>>(ei, E);
        gemm_kernel<<<g64, 256>>>(h, agg, gin_w1 + l*CC*CC, gin_b1 + l*CC, t1, NN, CC, CC, 1);
        gemm_kernel<<<g64, 256>>>(t1, nullptr, gin_w2 + l*CC*CC, gin_b2 + l*CC, t2, NN, CC, CC, 0);
        zero_stats_kernel<<<1, CC>>>();
        bn_stats_kernel<<<32, CC>>>(t2, h);
        bn_apply_kernel<<<ewgrid, 256>>>(t2, h, bn1_g + l*CC, bn1_b + l*CC, nullptr, h1);
        // ---- global attention (mma.sync flash, fp16 operands, online softmax) ----
        qkv_gemm_kernel<<<gqkv, 256>>>(h, wq + l*CC*CC, wk + l*CC*CC, wv + l*CC*CC,
                                       bq + l*CC, bk + l*CC, bv + l*CC, q, k, v);
        flash_mma_kernel<<<dim3(NN/128, HH), 128>>>(q, k, v, o);
        gemm_kernel<<<g64, 256>>>(o, nullptr, wo + l*CC*CC, bo + l*CC, t2, NN, CC, CC, 0);
        zero_stats_kernel<<<1, CC>>>();
        bn_stats_kernel<<<32, CC>>>(t2, h);
        bn_apply_kernel<<<ewgrid, 256>>>(t2, h, bn2_g + l*CC, bn2_b + l*CC, h1, q);
        // ---- feedforward ----
        gemm_kernel<<<g64w, 256>>>(q, nullptr, mw1 + l*2*CC*CC, mb1 + l*2*CC, t1, NN, 2*CC, CC, 1);
        gemm_kernel<<<g64, 256>>>(t1, nullptr, mw2 + l*2*CC*CC, mb2 + l*CC, t2, NN, CC, 2*CC, 0);
        zero_stats_kernel<<<1, CC>>>();
        bn_stats_kernel<<<32, CC>>>(t2, q);
        bn_apply_kernel<<<ewgrid, 256>>>(t2, q, bn3_g + l*CC, bn3_b + l*CC, nullptr,
                                         (l == LL-1) ? (float*)d_out : h);
    }
    (void)n_in; (void)out_size;
}

// round 8
// speedup vs baseline: 3.3458x; 1.3936x over previous
#include <cuda_runtime.h>
#include <cuda_fp16.h>
#include <math.h>
#include <stdint.h>

#define NN 4096
#define CC 256
#define HH 8
#define DHH 32
#define LL 3
#define EPSV 1e-5f
#define QSC (0.17677669529663687f * 1.4426950408889634f)

// ---------------- scratch (no allocation allowed) ----------------
__device__ float g_h[NN*CC];
__device__ float g_agg[NN*CC];
__device__ float g_t1[NN*2*CC];
__device__ float g_t2[NN*CC];
__device__ float g_q[NN*CC];
__device__ float g_k[NN*CC];
__device__ float g_v[NN*CC];
__device__ float g_o[NN*CC];
__device__ float g_h1[NN*CC];
__device__ float g_sum[CC];
__device__ float g_sumsq[CC];

// fp16 hi/lo weight cache (converted each launch; deterministic)
#define OFF_GW1 0
#define OFF_GW2 196608
#define OFF_WQ  393216
#define OFF_WK  589824
#define OFF_WV  786432
#define OFF_WO  983040
#define OFF_MW1 1179648
#define OFF_MW2 1572864
#define TOTW    1966080
__device__ __half g_wh[TOTW];
__device__ __half g_wl[TOTW];

// ---------------- mma helpers ----------------
__device__ __forceinline__ void mma16816(float* d, const uint32_t* a, const uint32_t* b) {
    asm volatile(
        "mma.sync.aligned.m16n8k16.row.col.f32.f16.f16.f32 "
        "{%0,%1,%2,%3}, {%4,%5,%6,%7}, {%8,%9}, {%0,%1,%2,%3};"
        : "+f"(d[0]), "+f"(d[1]), "+f"(d[2]), "+f"(d[3])
        : "r"(a[0]), "r"(a[1]), "r"(a[2]), "r"(a[3]), "r"(b[0]), "r"(b[1]));
}
__device__ __forceinline__ uint32_t packh2(float x, float y) {
    __half2 h = __floats2half2_rn(x, y);
    return *(uint32_t*)&h;
}

// ---------------- weight conversion: fp32 -> fp16 hi/lo ----------------
__global__ void convw_kernel(const float* __restrict__ src, int n, int off) {
    int i = blockIdx.x*256 + threadIdx.x;
    if (i < n) {
        float x = src[i];
        __half h = __float2half_rn(x);
        g_wh[off + i] = h;
        g_wl[off + i] = __float2half_rn(x - __half2float(h));
    }
}

// ---------------- HMMA GEMM: C[4096,Nout] = act((A1(+A2)) @ B^T + bias) ----------------
// 3-term hi/lo split: Ahi.Bhi + Alo.Bhi + Ahi.Blo (residual ~eps^2).
// CTA 128 thr, tile 128x64, warps 2(m) x 2(n), each 64x32 = 4x4 m16n8 tiles.
#define APAD 40
__device__ __forceinline__ void gemm_mma_body(
    const float* __restrict__ A1, const float* __restrict__ A2,
    const __half* __restrict__ Bh, const __half* __restrict__ Bl,
    const float* __restrict__ bias, float* __restrict__ C,
    int Nout, int K, int relu, int m0, int n0)
{
    __shared__ __half Ah[128][APAD];
    __shared__ __half Al[128][APAD];
    __shared__ __half Bhs[64][APAD];
    __shared__ __half Bls[64][APAD];

    const int tid = threadIdx.x;
    const int w = tid >> 5, lane = tid & 31;
    const int g = lane >> 2, tc = lane & 3;
    const int wm = w & 1, wn = w >> 1;

    float acc[4][4][4] = {};

    for (int k0 = 0; k0 < K; k0 += 32) {
        // A tile 128x32 fp32 -> hi/lo fp16 (16 float2 per thread)
        #pragma unroll
        for (int it = 0; it < 16; it++) {
            int idx = it*128 + tid;
            int r = idx >> 4, c2 = idx & 15;
            const float* p = &A1[(m0 + r)*K + k0 + c2*2];
            float ax = p[0], ay = p[1];
            if (A2) { const float* p2 = &A2[(m0 + r)*K + k0 + c2*2]; ax += p2[0]; ay += p2[1]; }
            __half hx = __float2half_rn(ax), hy = __float2half_rn(ay);
            Ah[r][c2*2]   = hx; Ah[r][c2*2+1] = hy;
            Al[r][c2*2]   = __float2half_rn(ax - __half2float(hx));
            Al[r][c2*2+1] = __float2half_rn(ay - __half2float(hy));
        }
        // B tiles 64x32 (hi and lo), pre-converted (8 half2 per thread each)
        #pragma unroll
        for (int it = 0; it < 8; it++) {
            int idx = it*128 + tid;
            int r = idx >> 4, c2 = idx & 15;
            *(__half2*)&Bhs[r][c2*2] = *(const __half2*)&Bh[(n0 + r)*K + k0 + c2*2];
            *(__half2*)&Bls[r][c2*2] = *(const __half2*)&Bl[(n0 + r)*K + k0 + c2*2];
        }
        __syncthreads();

        #pragma unroll
        for (int kt = 0; kt < 2; kt++) {
            uint32_t ah[4][4], al[4][4], bh[4][2], bl[4][2];
            #pragma unroll
            for (int mt = 0; mt < 4; mt++) {
                int rb = wm*64 + mt*16 + g;
                int c = kt*16 + 2*tc;
                ah[mt][0] = *(const uint32_t*)&Ah[rb    ][c];
                ah[mt][1] = *(const uint32_t*)&Ah[rb + 8][c];
                ah[mt][2] = *(const uint32_t*)&Ah[rb    ][c + 8];
                ah[mt][3] = *(const uint32_t*)&Ah[rb + 8][c + 8];
                al[mt][0] = *(const uint32_t*)&Al[rb    ][c];
                al[mt][1] = *(const uint32_t*)&Al[rb + 8][c];
                al[mt][2] = *(const uint32_t*)&Al[rb    ][c + 8];
                al[mt][3] = *(const uint32_t*)&Al[rb + 8][c + 8];
            }
            #pragma unroll
            for (int nt = 0; nt < 4; nt++) {
                int nb = wn*32 + nt*8 + g;
                int c = kt*16 + 2*tc;
                bh[nt][0] = *(const uint32_t*)&Bhs[nb][c];
                bh[nt][1] = *(const uint32_t*)&Bhs[nb][c + 8];
                bl[nt][0] = *(const uint32_t*)&Bls[nb][c];
                bl[nt][1] = *(const uint32_t*)&Bls[nb][c + 8];
            }
            #pragma unroll
            for (int mt = 0; mt < 4; mt++)
                #pragma unroll
                for (int nt = 0; nt < 4; nt++) {
                    mma16816(acc[mt][nt], ah[mt], bh[nt]);
                    mma16816(acc[mt][nt], al[mt], bh[nt]);
                    mma16816(acc[mt][nt], ah[mt], bl[nt]);
                }
        }
        __syncthreads();
    }

    #pragma unroll
    for (int mt = 0; mt < 4; mt++) {
        int row = m0 + wm*64 + mt*16 + g;
        #pragma unroll
        for (int nt = 0; nt < 4; nt++) {
            int col = n0 + wn*32 + nt*8 + 2*tc;
            float b0 = bias[col], b1 = bias[col + 1];
            float v0 = acc[mt][nt][0] + b0, v1 = acc[mt][nt][1] + b1;
            float v2 = acc[mt][nt][2] + b0, v3 = acc[mt][nt][3] + b1;
            if (relu) {
                v0 = fmaxf(v0, 0.f); v1 = fmaxf(v1, 0.f);
                v2 = fmaxf(v2, 0.f); v3 = fmaxf(v3, 0.f);
            }
            *(float2*)&C[row*Nout + col]       = make_float2(v0, v1);
            *(float2*)&C[(row + 8)*Nout + col] = make_float2(v2, v3);
        }
    }
}

__global__ void __launch_bounds__(128) gemm_mma_kernel(
    const float* __restrict__ A1, const float* __restrict__ A2,
    const __half* __restrict__ Bh, const __half* __restrict__ Bl,
    const float* __restrict__ bias, float* __restrict__ C,
    int Nout, int K, int relu)
{
    gemm_mma_body(A1, A2, Bh, Bl, bias, C, Nout, K, relu,
                  blockIdx.y*128, blockIdx.x*64);
}

// fused Q/K/V projection (blockIdx.z selects target)
__global__ void __launch_bounds__(128) qkv_mma_kernel(
    const float* __restrict__ A, const __half* __restrict__ wh,
    const __half* __restrict__ wl,
    const float* __restrict__ bq, const float* __restrict__ bk,
    const float* __restrict__ bv,
    float* __restrict__ q, float* __restrict__ k, float* __restrict__ v, int l)
{
    const __half *Bh, *Bl; const float* bias; float* C;
    int woff = l*CC*CC;
    if (blockIdx.z == 0)      { Bh = wh + OFF_WQ + woff; Bl = wl + OFF_WQ + woff; bias = bq; C = q; }
    else if (blockIdx.z == 1) { Bh = wh + OFF_WK + woff; Bl = wl + OFF_WK + woff; bias = bk; C = k; }
    else                      { Bh = wh + OFF_WV + woff; Bl = wl + OFF_WV + woff; bias = bv; C = v; }
    gemm_mma_body(A, nullptr, Bh, Bl, bias, C, CC, CC, 0,
                  blockIdx.y*128, blockIdx.x*64);
}

// ---------------- flash attention (fp16 mma, online softmax) ----------------
#define QPAD 36
#define VPAD 132
__global__ void __launch_bounds__(128) flash_mma_kernel(
    const float* __restrict__ Q, const float* __restrict__ Kp,
    const float* __restrict__ V, float* __restrict__ Og)
{
    __shared__ __half Qs[128][QPAD];
    __shared__ __half Ks[128][QPAD];
    __shared__ __half VTs[32][VPAD];

    const int tid = threadIdx.x;
    const int w = tid >> 5, lane = tid & 31;
    const int g = lane >> 2, tc = lane & 3;
    const int hoff = blockIdx.y * DHH;
    const int q0 = blockIdx.x * 128;

    #pragma unroll
    for (int it = 0; it < 16; it++) {
        int idx = it*128 + tid;
        int r = idx >> 4, pr = idx & 15;
        float2 f = *(const float2*)&Q[(q0 + r)*CC + hoff + pr*2];
        *(__half2*)&Qs[r][pr*2] = __floats2half2_rn(f.x * QSC, f.y * QSC);
    }
    __syncthreads();

    uint32_t qa[2][2][4];
    #pragma unroll
    for (int mt = 0; mt < 2; mt++) {
        #pragma unroll
        for (int kt = 0; kt < 2; kt++) {
            int r0 = w*32 + mt*16 + g;
            qa[mt][kt][0] = *(const uint32_t*)&Qs[r0    ][kt*16 + 2*tc    ];
            qa[mt][kt][1] = *(const uint32_t*)&Qs[r0 + 8][kt*16 + 2*tc    ];
            qa[mt][kt][2] = *(const uint32_t*)&Qs[r0    ][kt*16 + 2*tc + 8];
            qa[mt][kt][3] = *(const uint32_t*)&Qs[r0 + 8][kt*16 + 2*tc + 8];
        }
    }

    float oacc[2][4][4] = {};
    float lacc[4] = {};
    float mrow[4] = {-1e30f, -1e30f, -1e30f, -1e30f};

    for (int j0 = 0; j0 < NN; j0 += 128) {
        __syncthreads();
        #pragma unroll
        for (int it = 0; it < 16; it++) {
            int idx = it*128 + tid;
            int r = idx >> 4, pr = idx & 15;
            float2 f = *(const float2*)&Kp[(j0 + r)*CC + hoff + pr*2];
            *(__half2*)&Ks[r][pr*2] = __floats2half2_rn(f.x, f.y);
        }
        #pragma unroll
        for (int it = 0; it < 16; it++) {
            int idx = it*128 + tid;
            int j = idx >> 4, dp = idx & 15;
            float2 f = *(const float2*)&V[(j0 + j)*CC + hoff + dp*2];
            VTs[dp*2    ][j] = __float2half(f.x);
            VTs[dp*2 + 1][j] = __float2half(f.y);
        }
        __syncthreads();

        #pragma unroll
        for (int ng = 0; ng < 8; ng++) {
            const int kb = ng*16;
            float s[2][2][4] = {};
            #pragma unroll
            for (int kt = 0; kt < 2; kt++) {
                uint32_t b[2][2];
                #pragma unroll
                for (int j = 0; j < 2; j++) {
                    int key = kb + j*8 + g;
                    b[j][0] = *(const uint32_t*)&Ks[key][kt*16 + 2*tc    ];
                    b[j][1] = *(const uint32_t*)&Ks[key][kt*16 + 2*tc + 8];
                }
                #pragma unroll
                for (int mt = 0; mt < 2; mt++)
                    #pragma unroll
                    for (int j = 0; j < 2; j++)
                        mma16816(s[mt][j], qa[mt][kt], b[j]);
            }
            uint32_t pa[2][4];
            #pragma unroll
            for (int mt = 0; mt < 2; mt++) {
                #pragma unroll
                for (int hi = 0; hi < 2; hi++) {
                    float rm = fmaxf(fmaxf(s[mt][0][2*hi], s[mt][0][2*hi+1]),
                                     fmaxf(s[mt][1][2*hi], s[mt][1][2*hi+1]));
                    rm = fmaxf(rm, __shfl_xor_sync(0xffffffffu, rm, 1));
                    rm = fmaxf(rm, __shfl_xor_sync(0xffffffffu, rm, 2));
                    float mold = mrow[mt*2 + hi];
                    float mnew = fmaxf(mold, rm);
                    float cf = exp2f(mold - mnew);
                    mrow[mt*2 + hi] = mnew;
                    float p00 = exp2f(s[mt][0][2*hi]   - mnew);
                    float p01 = exp2f(s[mt][0][2*hi+1] - mnew);
                    float p10 = exp2f(s[mt][1][2*hi]   - mnew);
                    float p11 = exp2f(s[mt][1][2*hi+1] - mnew);
                    lacc[mt*2 + hi] = lacc[mt*2 + hi]*cf + p00 + p01 + p10 + p11;
                    pa[mt][0*2 + hi] = packh2(p00, p01);
                    pa[mt][1*2 + hi] = packh2(p10, p11);
                    #pragma unroll
                    for (int dj = 0; dj < 4; dj++) {
                        oacc[mt][dj][2*hi]   *= cf;
                        oacc[mt][dj][2*hi+1] *= cf;
                    }
                }
            }
            #pragma unroll
            for (int dj = 0; dj < 4; dj++) {
                uint32_t vb[2];
                vb[0] = *(const uint32_t*)&VTs[dj*8 + g][kb + 2*tc    ];
                vb[1] = *(const uint32_t*)&VTs[dj*8 + g][kb + 2*tc + 8];
                #pragma unroll
                for (int mt = 0; mt < 2; mt++)
                    mma16816(oacc[mt][dj], pa[mt], vb);
            }
        }
    }

    #pragma unroll
    for (int i = 0; i < 4; i++) {
        lacc[i] += __shfl_xor_sync(0xffffffffu, lacc[i], 1);
        lacc[i] += __shfl_xor_sync(0xffffffffu, lacc[i], 2);
    }
    #pragma unroll
    for (int mt = 0; mt < 2; mt++) {
        int rbase = q0 + w*32 + mt*16;
        float inv0 = 1.f / lacc[mt*2 + 0];
        float inv1 = 1.f / lacc[mt*2 + 1];
        #pragma unroll
        for (int dj = 0; dj < 4; dj++) {
            int col = hoff + dj*8 + 2*tc;
            *(float2*)&Og[(rbase + g    )*CC + col] =
                make_float2(oacc[mt][dj][0]*inv0, oacc[mt][dj][1]*inv0);
            *(float2*)&Og[(rbase + g + 8)*CC + col] =
                make_float2(oacc[mt][dj][2]*inv1, oacc[mt][dj][3]*inv1);
        }
    }
}

// ---------------- small kernels ----------------
__global__ void lin1_kernel(const float* __restrict__ x, const float* __restrict__ w,
                            const float* __restrict__ b) {
    int n = blockIdx.x, c = threadIdx.x;
    g_h[n*CC + c] = x[n]*w[c] + b[c];
}

__global__ void zero_kernel(float* __restrict__ p, int n) {
    int i = blockIdx.x*blockDim.x + threadIdx.x;
    if (i < n) p[i] = 0.f;
}

__global__ void zero_stats_kernel() {
    g_sum[threadIdx.x]   = 0.f;
    g_sumsq[threadIdx.x] = 0.f;
}

__global__ void scatter_kernel(const int* __restrict__ ei, int E) {
    const int* src = ei;
    const int* dst = ei + E;
    int c = threadIdx.x;
    int e0 = blockIdx.x * 4;
    #pragma unroll
    for (int k = 0; k < 4; k++) {
        int e = e0 + k;
        int s = src[e], d = dst[e];
        atomicAdd(&g_agg[d*CC + c], g_h[s*CC + c]);
    }
}

__global__ void bn_stats_kernel(const float* __restrict__ in1, const float* __restrict__ in2) {
    int c = threadIdx.x;
    int r0 = blockIdx.x * 128;
    float s = 0.f, ss = 0.f;
    for (int r = r0; r < r0 + 128; r++) {
        float v = in1[r*CC + c] + in2[r*CC + c];
        s += v; ss += v*v;
    }
    atomicAdd(&g_sum[c], s);
    atomicAdd(&g_sumsq[c], ss);
}

__global__ void bn_apply_kernel(const float* __restrict__ in1, const float* __restrict__ in2,
                                const float* __restrict__ gamma, const float* __restrict__ beta,
                                const float* __restrict__ addend, float* __restrict__ out) {
    int i = blockIdx.x*256 + threadIdx.x;
    int c = i & (CC-1);
    float mean = g_sum[c] * (1.f/NN);
    float var  = g_sumsq[c] * (1.f/NN) - mean*mean;
    float v = in1[i] + in2[i];
    float r = (v - mean) * rsqrtf(var + EPSV) * gamma[c] + beta[c];
    if (addend) r += addend[i];
    out[i] = r;
}

// ---------------- host ----------------
extern "C" void kernel_launch(void* const* d_in, const int* in_sizes, int n_in,
                              void* d_out, int out_size) {
    const float* x      = (const float*)d_in[0];
    const int*   ei     = (const int*)  d_in[1];
    const float* lin1_w = (const float*)d_in[2];
    const float* lin1_b = (const float*)d_in[3];
    const float* gin_w1 = (const float*)d_in[4];
    const float* gin_b1 = (const float*)d_in[5];
    const float* gin_w2 = (const float*)d_in[6];
    const float* gin_b2 = (const float*)d_in[7];
    const float* wq = (const float*)d_in[8];
    const float* wk = (const float*)d_in[9];
    const float* wv = (const float*)d_in[10];
    const float* wo = (const float*)d_in[11];
    const float* bq = (const float*)d_in[12];
    const float* bk = (const float*)d_in[13];
    const float* bv = (const float*)d_in[14];
    const float* bo = (const float*)d_in[15];
    const float* bn1_g = (const float*)d_in[16];
    const float* bn1_b = (const float*)d_in[17];
    const float* bn2_g = (const float*)d_in[18];
    const float* bn2_b = (const float*)d_in[19];
    const float* bn3_g = (const float*)d_in[20];
    const float* bn3_b = (const float*)d_in[21];
    const float* mw1 = (const float*)d_in[22];
    const float* mb1 = (const float*)d_in[23];
    const float* mw2 = (const float*)d_in[24];
    const float* mb2 = (const float*)d_in[25];
    int E = in_sizes[1] / 2;

    float *h, *agg, *t1, *t2, *q, *k, *v, *o, *h1;
    cudaGetSymbolAddress((void**)&h,   g_h);
    cudaGetSymbolAddress((void**)&agg, g_agg);
    cudaGetSymbolAddress((void**)&t1,  g_t1);
    cudaGetSymbolAddress((void**)&t2,  g_t2);
    cudaGetSymbolAddress((void**)&q,   g_q);
    cudaGetSymbolAddress((void**)&k,   g_k);
    cudaGetSymbolAddress((void**)&v,   g_v);
    cudaGetSymbolAddress((void**)&o,   g_o);
    cudaGetSymbolAddress((void**)&h1,  g_h1);
    __half *wh, *wl;
    cudaGetSymbolAddress((void**)&wh, g_wh);
    cudaGetSymbolAddress((void**)&wl, g_wl);

    // weight conversion (all layers, once per call)
    const int SZ1 = LL*CC*CC;       // 196608
    const int SZ2 = LL*2*CC*CC;     // 393216
    convw_kernel<<<SZ1/256, 256>>>(gin_w1, SZ1, OFF_GW1);
    convw_kernel<<<SZ1/256, 256>>>(gin_w2, SZ1, OFF_GW2);
    convw_kernel<<<SZ1/256, 256>>>(wq,     SZ1, OFF_WQ);
    convw_kernel<<<SZ1/256, 256>>>(wk,     SZ1, OFF_WK);
    convw_kernel<<<SZ1/256, 256>>>(wv,     SZ1, OFF_WV);
    convw_kernel<<<SZ1/256, 256>>>(wo,     SZ1, OFF_WO);
    convw_kernel<<<SZ2/256, 256>>>(mw1,    SZ2, OFF_MW1);
    convw_kernel<<<SZ2/256, 256>>>(mw2,    SZ2, OFF_MW2);

    dim3 gN256(CC/64,   NN/128);       // 4 x 32
    dim3 gN512(2*CC/64, NN/128);       // 8 x 32
    dim3 gqkv (CC/64,   NN/128, 3);
    int ewgrid = NN*CC/256;

    lin1_kernel<<<NN, CC>>>(x, lin1_w, lin1_b);

    for (int l = 0; l < LL; l++) {
        int w1 = l*CC*CC, w2 = l*2*CC*CC;
        // ---- GIN branch ----
        zero_kernel<<<ewgrid, 256>>>(agg, NN*CC);
        scatter_kernel<<<E/4, CC>>>(ei, E);
        gemm_mma_kernel<<<gN256, 128>>>(h, agg, wh + OFF_GW1 + w1, wl + OFF_GW1 + w1,
                                        gin_b1 + l*CC, t1, CC, CC, 1);
        gemm_mma_kernel<<<gN256, 128>>>(t1, nullptr, wh + OFF_GW2 + w1, wl + OFF_GW2 + w1,
                                        gin_b2 + l*CC, t2, CC, CC, 0);
        zero_stats_kernel<<<1, CC>>>();
        bn_stats_kernel<<<32, CC>>>(t2, h);
        bn_apply_kernel<<<ewgrid, 256>>>(t2, h, bn1_g + l*CC, bn1_b + l*CC, nullptr, h1);
        // ---- global attention ----
        qkv_mma_kernel<<<gqkv, 128>>>(h, wh, wl, bq + l*CC, bk + l*CC, bv + l*CC, q, k, v, l);
        flash_mma_kernel<<<dim3(NN/128, HH), 128>>>(q, k, v, o);
        gemm_mma_kernel<<<gN256, 128>>>(o, nullptr, wh + OFF_WO + w1, wl + OFF_WO + w1,
                                        bo + l*CC, t2, CC, CC, 0);
        zero_stats_kernel<<<1, CC>>>();
        bn_stats_kernel<<<32, CC>>>(t2, h);
        bn_apply_kernel<<<ewgrid, 256>>>(t2, h, bn2_g + l*CC, bn2_b + l*CC, h1, q);
        // ---- feedforward ----
        gemm_mma_kernel<<<gN512, 128>>>(q, nullptr, wh + OFF_MW1 + w2, wl + OFF_MW1 + w2,
                                        mb1 + l*2*CC, t1, 2*CC, CC, 1);
        gemm_mma_kernel<<<gN256, 128>>>(t1, nullptr, wh + OFF_MW2 + w2, wl + OFF_MW2 + w2,
                                        mb2 + l*CC, t2, CC, 2*CC, 0);
        zero_stats_kernel<<<1, CC>>>();
        bn_stats_kernel<<<32, CC>>>(t2, q);
        bn_apply_kernel<<<ewgrid, 256>>>(t2, q, bn3_g + l*CC, bn3_b + l*CC, nullptr,
                                         (l == LL-1) ? (float*)d_out : h);
    }
    (void)n_in; (void)out_size;
}

// round 9
// speedup vs baseline: 3.6669x; 1.0960x over previous
#include <cuda_runtime.h>
#include <cuda_fp16.h>
#include <math.h>
#include <stdint.h>

#define NN 4096
#define CC 256
#define HH 8
#define DHH 32
#define LL 3
#define EPSV 1e-5f
#define QSC (0.17677669529663687f * 1.4426950408889634f)

// ---------------- scratch (no allocation allowed) ----------------
__device__ float g_h[NN*CC];
__device__ float g_agg[NN*CC];
__device__ float g_t1[NN*2*CC];
__device__ float g_t2[NN*CC];
__device__ float g_q[NN*CC];
__device__ float g_k[NN*CC];
__device__ float g_v[NN*CC];
__device__ float g_o[NN*CC];
__device__ float g_h1[NN*CC];
__device__ float g_sum[CC];
__device__ float g_sumsq[CC];

// fp16 hi/lo weight cache (converted each launch; deterministic)
#define OFF_GW1 0
#define OFF_GW2 196608
#define OFF_WQ  393216
#define OFF_WK  589824
#define OFF_WV  786432
#define OFF_WO  983040
#define OFF_MW1 1179648
#define OFF_MW2 1572864
#define TOTW    1966080
__device__ __half g_wh[TOTW];
__device__ __half g_wl[TOTW];

// ---------------- mma helpers ----------------
__device__ __forceinline__ void mma16816(float* d, const uint32_t* a, const uint32_t* b) {
    asm volatile(
        "mma.sync.aligned.m16n8k16.row.col.f32.f16.f16.f32 "
        "{%0,%1,%2,%3}, {%4,%5,%6,%7}, {%8,%9}, {%0,%1,%2,%3};"
        : "+f"(d[0]), "+f"(d[1]), "+f"(d[2]), "+f"(d[3])
        : "r"(a[0]), "r"(a[1]), "r"(a[2]), "r"(a[3]), "r"(b[0]), "r"(b[1]));
}
__device__ __forceinline__ uint32_t packh2(float x, float y) {
    __half2 h = __floats2half2_rn(x, y);
    return *(uint32_t*)&h;
}

// ---------------- weight conversion: all 8 regions, one launch ----------------
__global__ void convw_all_kernel(
    const float* __restrict__ gw1, const float* __restrict__ gw2,
    const float* __restrict__ wq,  const float* __restrict__ wk,
    const float* __restrict__ wv,  const float* __restrict__ wo,
    const float* __restrict__ mw1, const float* __restrict__ mw2)
{
    int i = blockIdx.x*256 + threadIdx.x;
    if (i >= TOTW) return;
    const float* src; int off;
    if      (i < OFF_GW2) { src = gw1; off = OFF_GW1; }
    else if (i < OFF_WQ)  { src = gw2; off = OFF_GW2; }
    else if (i < OFF_WK)  { src = wq;  off = OFF_WQ;  }
    else if (i < OFF_WV)  { src = wk;  off = OFF_WK;  }
    else if (i < OFF_WO)  { src = wv;  off = OFF_WV;  }
    else if (i < OFF_MW1) { src = wo;  off = OFF_WO;  }
    else if (i < OFF_MW2) { src = mw1; off = OFF_MW1; }
    else                  { src = mw2; off = OFF_MW2; }
    float x = src[i - off];
    __half h = __float2half_rn(x);
    g_wh[i] = h;
    g_wl[i] = __float2half_rn(x - __half2float(h));
}

// ---------------- HMMA GEMM (3-term hi/lo split) ----------------
#define APAD 40
__device__ __forceinline__ void gemm_mma_body(
    const float* __restrict__ A1, const float* __restrict__ A2,
    const __half* __restrict__ Bh, const __half* __restrict__ Bl,
    const float* __restrict__ bias, float* __restrict__ C,
    int Nout, int K, int relu, int m0, int n0)
{
    __shared__ __half Ah[128][APAD];
    __shared__ __half Al[128][APAD];
    __shared__ __half Bhs[64][APAD];
    __shared__ __half Bls[64][APAD];

    const int tid = threadIdx.x;
    const int w = tid >> 5, lane = tid & 31;
    const int g = lane >> 2, tc = lane & 3;
    const int wm = w & 1, wn = w >> 1;

    float acc[4][4][4] = {};

    for (int k0 = 0; k0 < K; k0 += 32) {
        #pragma unroll
        for (int it = 0; it < 16; it++) {
            int idx = it*128 + tid;
            int r = idx >> 4, c2 = idx & 15;
            const float* p = &A1[(m0 + r)*K + k0 + c2*2];
            float ax = p[0], ay = p[1];
            if (A2) { const float* p2 = &A2[(m0 + r)*K + k0 + c2*2]; ax += p2[0]; ay += p2[1]; }
            __half hx = __float2half_rn(ax), hy = __float2half_rn(ay);
            Ah[r][c2*2]   = hx; Ah[r][c2*2+1] = hy;
            Al[r][c2*2]   = __float2half_rn(ax - __half2float(hx));
            Al[r][c2*2+1] = __float2half_rn(ay - __half2float(hy));
        }
        #pragma unroll
        for (int it = 0; it < 8; it++) {
            int idx = it*128 + tid;
            int r = idx >> 4, c2 = idx & 15;
            *(__half2*)&Bhs[r][c2*2] = *(const __half2*)&Bh[(n0 + r)*K + k0 + c2*2];
            *(__half2*)&Bls[r][c2*2] = *(const __half2*)&Bl[(n0 + r)*K + k0 + c2*2];
        }
        __syncthreads();

        #pragma unroll
        for (int kt = 0; kt < 2; kt++) {
            uint32_t ah[4][4], al[4][4], bh[4][2], bl[4][2];
            #pragma unroll
            for (int mt = 0; mt < 4; mt++) {
                int rb = wm*64 + mt*16 + g;
                int c = kt*16 + 2*tc;
                ah[mt][0] = *(const uint32_t*)&Ah[rb    ][c];
                ah[mt][1] = *(const uint32_t*)&Ah[rb + 8][c];
                ah[mt][2] = *(const uint32_t*)&Ah[rb    ][c + 8];
                ah[mt][3] = *(const uint32_t*)&Ah[rb + 8][c + 8];
                al[mt][0] = *(const uint32_t*)&Al[rb    ][c];
                al[mt][1] = *(const uint32_t*)&Al[rb + 8][c];
                al[mt][2] = *(const uint32_t*)&Al[rb    ][c + 8];
                al[mt][3] = *(const uint32_t*)&Al[rb + 8][c + 8];
            }
            #pragma unroll
            for (int nt = 0; nt < 4; nt++) {
                int nb = wn*32 + nt*8 + g;
                int c = kt*16 + 2*tc;
                bh[nt][0] = *(const uint32_t*)&Bhs[nb][c];
                bh[nt][1] = *(const uint32_t*)&Bhs[nb][c + 8];
                bl[nt][0] = *(const uint32_t*)&Bls[nb][c];
                bl[nt][1] = *(const uint32_t*)&Bls[nb][c + 8];
            }
            #pragma unroll
            for (int mt = 0; mt < 4; mt++)
                #pragma unroll
                for (int nt = 0; nt < 4; nt++) {
                    mma16816(acc[mt][nt], ah[mt], bh[nt]);
                    mma16816(acc[mt][nt], al[mt], bh[nt]);
                    mma16816(acc[mt][nt], ah[mt], bl[nt]);
                }
        }
        __syncthreads();
    }

    #pragma unroll
    for (int mt = 0; mt < 4; mt++) {
        int row = m0 + wm*64 + mt*16 + g;
        #pragma unroll
        for (int nt = 0; nt < 4; nt++) {
            int col = n0 + wn*32 + nt*8 + 2*tc;
            float b0 = bias[col], b1 = bias[col + 1];
            float v0 = acc[mt][nt][0] + b0, v1 = acc[mt][nt][1] + b1;
            float v2 = acc[mt][nt][2] + b0, v3 = acc[mt][nt][3] + b1;
            if (relu) {
                v0 = fmaxf(v0, 0.f); v1 = fmaxf(v1, 0.f);
                v2 = fmaxf(v2, 0.f); v3 = fmaxf(v3, 0.f);
            }
            *(float2*)&C[row*Nout + col]       = make_float2(v0, v1);
            *(float2*)&C[(row + 8)*Nout + col] = make_float2(v2, v3);
        }
    }
}

__global__ void __launch_bounds__(128) gemm_mma_kernel(
    const float* __restrict__ A1, const float* __restrict__ A2,
    const __half* __restrict__ Bh, const __half* __restrict__ Bl,
    const float* __restrict__ bias, float* __restrict__ C,
    int Nout, int K, int relu)
{
    gemm_mma_body(A1, A2, Bh, Bl, bias, C, Nout, K, relu,
                  blockIdx.y*128, blockIdx.x*64);
}

__global__ void __launch_bounds__(128) qkv_mma_kernel(
    const float* __restrict__ A, const __half* __restrict__ wh,
    const __half* __restrict__ wl,
    const float* __restrict__ bq, const float* __restrict__ bk,
    const float* __restrict__ bv,
    float* __restrict__ q, float* __restrict__ k, float* __restrict__ v, int l)
{
    const __half *Bh, *Bl; const float* bias; float* C;
    int woff = l*CC*CC;
    if (blockIdx.z == 0)      { Bh = wh + OFF_WQ + woff; Bl = wl + OFF_WQ + woff; bias = bq; C = q; }
    else if (blockIdx.z == 1) { Bh = wh + OFF_WK + woff; Bl = wl + OFF_WK + woff; bias = bk; C = k; }
    else                      { Bh = wh + OFF_WV + woff; Bl = wl + OFF_WV + woff; bias = bv; C = v; }
    gemm_mma_body(A, nullptr, Bh, Bl, bias, C, CC, CC, 0,
                  blockIdx.y*128, blockIdx.x*64);
}

// ---------------- flash attention (fp16 mma, online softmax, skip-rescale) ----------------
// 256 threads / 8 warps, q-tile 256 rows. grid (NN/256, HH).
#define QPAD 36
#define VPAD 132
__global__ void __launch_bounds__(256) flash_mma_kernel(
    const float* __restrict__ Q, const float* __restrict__ Kp,
    const float* __restrict__ V, float* __restrict__ Og)
{
    __shared__ __half Qs[256][QPAD];
    __shared__ __half Ks[128][QPAD];
    __shared__ __half VTs[32][VPAD];

    const int tid = threadIdx.x;
    const int w = tid >> 5, lane = tid & 31;
    const int g = lane >> 2, tc = lane & 3;
    const int hoff = blockIdx.y * DHH;
    const int q0 = blockIdx.x * 256;

    #pragma unroll
    for (int it = 0; it < 16; it++) {
        int idx = it*256 + tid;
        int r = idx >> 4, pr = idx & 15;
        float2 f = *(const float2*)&Q[(q0 + r)*CC + hoff + pr*2];
        *(__half2*)&Qs[r][pr*2] = __floats2half2_rn(f.x * QSC, f.y * QSC);
    }
    __syncthreads();

    uint32_t qa[2][2][4];
    #pragma unroll
    for (int mt = 0; mt < 2; mt++) {
        #pragma unroll
        for (int kt = 0; kt < 2; kt++) {
            int r0 = w*32 + mt*16 + g;
            qa[mt][kt][0] = *(const uint32_t*)&Qs[r0    ][kt*16 + 2*tc    ];
            qa[mt][kt][1] = *(const uint32_t*)&Qs[r0 + 8][kt*16 + 2*tc    ];
            qa[mt][kt][2] = *(const uint32_t*)&Qs[r0    ][kt*16 + 2*tc + 8];
            qa[mt][kt][3] = *(const uint32_t*)&Qs[r0 + 8][kt*16 + 2*tc + 8];
        }
    }

    float oacc[2][4][4] = {};
    float lacc[4] = {};
    float mrow[4] = {-1e30f, -1e30f, -1e30f, -1e30f};

    for (int j0 = 0; j0 < NN; j0 += 128) {
        __syncthreads();
        #pragma unroll
        for (int it = 0; it < 8; it++) {
            int idx = it*256 + tid;
            int r = idx >> 4, pr = idx & 15;
            float2 f = *(const float2*)&Kp[(j0 + r)*CC + hoff + pr*2];
            *(__half2*)&Ks[r][pr*2] = __floats2half2_rn(f.x, f.y);
        }
        #pragma unroll
        for (int it = 0; it < 8; it++) {
            int idx = it*256 + tid;
            int j = idx >> 4, dp = idx & 15;
            float2 f = *(const float2*)&V[(j0 + j)*CC + hoff + dp*2];
            VTs[dp*2    ][j] = __float2half(f.x);
            VTs[dp*2 + 1][j] = __float2half(f.y);
        }
        __syncthreads();

        #pragma unroll
        for (int ng = 0; ng < 8; ng++) {
            const int kb = ng*16;
            float s[2][2][4] = {};
            #pragma unroll
            for (int kt = 0; kt < 2; kt++) {
                uint32_t b[2][2];
                #pragma unroll
                for (int j = 0; j < 2; j++) {
                    int key = kb + j*8 + g;
                    b[j][0] = *(const uint32_t*)&Ks[key][kt*16 + 2*tc    ];
                    b[j][1] = *(const uint32_t*)&Ks[key][kt*16 + 2*tc + 8];
                }
                #pragma unroll
                for (int mt = 0; mt < 2; mt++)
                    #pragma unroll
                    for (int j = 0; j < 2; j++)
                        mma16816(s[mt][j], qa[mt][kt], b[j]);
            }
            uint32_t pa[2][4];
            #pragma unroll
            for (int mt = 0; mt < 2; mt++) {
                #pragma unroll
                for (int hi = 0; hi < 2; hi++) {
                    float rm = fmaxf(fmaxf(s[mt][0][2*hi], s[mt][0][2*hi+1]),
                                     fmaxf(s[mt][1][2*hi], s[mt][1][2*hi+1]));
                    rm = fmaxf(rm, __shfl_xor_sync(0xffffffffu, rm, 1));
                    rm = fmaxf(rm, __shfl_xor_sync(0xffffffffu, rm, 2));
                    float mold = mrow[mt*2 + hi];
                    float mnew = fmaxf(mold, rm);
                    float p00 = exp2f(s[mt][0][2*hi]   - mnew);
                    float p01 = exp2f(s[mt][0][2*hi+1] - mnew);
                    float p10 = exp2f(s[mt][1][2*hi]   - mnew);
                    float p11 = exp2f(s[mt][1][2*hi+1] - mnew);
                    float ps = p00 + p01 + p10 + p11;
                    if (rm > mold) {          // max changed: rescale (quad-uniform branch)
                        float cf = exp2f(mold - mnew);
                        mrow[mt*2 + hi] = mnew;
                        lacc[mt*2 + hi] = lacc[mt*2 + hi]*cf + ps;
                        #pragma unroll
                        for (int dj = 0; dj < 4; dj++) {
                            oacc[mt][dj][2*hi]   *= cf;
                            oacc[mt][dj][2*hi+1] *= cf;
                        }
                    } else {
                        lacc[mt*2 + hi] += ps;
                    }
                    pa[mt][0*2 + hi] = packh2(p00, p01);
                    pa[mt][1*2 + hi] = packh2(p10, p11);
                }
            }
            #pragma unroll
            for (int dj = 0; dj < 4; dj++) {
                uint32_t vb[2];
                vb[0] = *(const uint32_t*)&VTs[dj*8 + g][kb + 2*tc    ];
                vb[1] = *(const uint32_t*)&VTs[dj*8 + g][kb + 2*tc + 8];
                #pragma unroll
                for (int mt = 0; mt < 2; mt++)
                    mma16816(oacc[mt][dj], pa[mt], vb);
            }
        }
    }

    #pragma unroll
    for (int i = 0; i < 4; i++) {
        lacc[i] += __shfl_xor_sync(0xffffffffu, lacc[i], 1);
        lacc[i] += __shfl_xor_sync(0xffffffffu, lacc[i], 2);
    }
    #pragma unroll
    for (int mt = 0; mt < 2; mt++) {
        int rbase = q0 + w*32 + mt*16;
        float inv0 = 1.f / lacc[mt*2 + 0];
        float inv1 = 1.f / lacc[mt*2 + 1];
        #pragma unroll
        for (int dj = 0; dj < 4; dj++) {
            int col = hoff + dj*8 + 2*tc;
            *(float2*)&Og[(rbase + g    )*CC + col] =
                make_float2(oacc[mt][dj][0]*inv0, oacc[mt][dj][1]*inv0);
            *(float2*)&Og[(rbase + g + 8)*CC + col] =
                make_float2(oacc[mt][dj][2]*inv1, oacc[mt][dj][3]*inv1);
        }
    }
}

// ---------------- small kernels ----------------
__global__ void lin1_kernel(const float* __restrict__ x, const float* __restrict__ w,
                            const float* __restrict__ b) {
    int n = blockIdx.x, c = threadIdx.x;
    g_h[n*CC + c] = x[n]*w[c] + b[c];
}

__global__ void zero_kernel(float* __restrict__ p, int n) {
    int i = blockIdx.x*blockDim.x + threadIdx.x;
    if (i < n) p[i] = 0.f;
}

__global__ void zero_stats_kernel() {
    g_sum[threadIdx.x]   = 0.f;
    g_sumsq[threadIdx.x] = 0.f;
}

__global__ void scatter_kernel(const int* __restrict__ ei, int E) {
    const int* src = ei;
    const int* dst = ei + E;
    int c = threadIdx.x;
    int e0 = blockIdx.x * 4;
    #pragma unroll
    for (int k = 0; k < 4; k++) {
        int e = e0 + k;
        int s = src[e], d = dst[e];
        atomicAdd(&g_agg[d*CC + c], g_h[s*CC + c]);
    }
}

// 128 blocks x 32 rows each
__global__ void bn_stats_kernel(const float* __restrict__ in1, const float* __restrict__ in2) {
    int c = threadIdx.x;
    int r0 = blockIdx.x * 32;
    float s = 0.f, ss = 0.f;
    #pragma unroll 4
    for (int r = r0; r < r0 + 32; r++) {
        float v = in1[r*CC + c] + in2[r*CC + c];
        s += v; ss += v*v;
    }
    atomicAdd(&g_sum[c], s);
    atomicAdd(&g_sumsq[c], ss);
}

__global__ void bn_apply_kernel(const float* __restrict__ in1, const float* __restrict__ in2,
                                const float* __restrict__ gamma, const float* __restrict__ beta,
                                const float* __restrict__ addend, float* __restrict__ out) {
    int i = blockIdx.x*256 + threadIdx.x;
    int c = i & (CC-1);
    float mean = g_sum[c] * (1.f/NN);
    float var  = g_sumsq[c] * (1.f/NN) - mean*mean;
    float v = in1[i] + in2[i];
    float r = (v - mean) * rsqrtf(var + EPSV) * gamma[c] + beta[c];
    if (addend) r += addend[i];
    out[i] = r;
}

// ---------------- host ----------------
extern "C" void kernel_launch(void* const* d_in, const int* in_sizes, int n_in,
                              void* d_out, int out_size) {
    const float* x      = (const float*)d_in[0];
    const int*   ei     = (const int*)  d_in[1];
    const float* lin1_w = (const float*)d_in[2];
    const float* lin1_b = (const float*)d_in[3];
    const float* gin_w1 = (const float*)d_in[4];
    const float* gin_b1 = (const float*)d_in[5];
    const float* gin_w2 = (const float*)d_in[6];
    const float* gin_b2 = (const float*)d_in[7];
    const float* wq = (const float*)d_in[8];
    const float* wk = (const float*)d_in[9];
    const float* wv = (const float*)d_in[10];
    const float* wo = (const float*)d_in[11];
    const float* bq = (const float*)d_in[12];
    const float* bk = (const float*)d_in[13];
    const float* bv = (const float*)d_in[14];
    const float* bo = (const float*)d_in[15];
    const float* bn1_g = (const float*)d_in[16];
    const float* bn1_b = (const float*)d_in[17];
    const float* bn2_g = (const float*)d_in[18];
    const float* bn2_b = (const float*)d_in[19];
    const float* bn3_g = (const float*)d_in[20];
    const float* bn3_b = (const float*)d_in[21];
    const float* mw1 = (const float*)d_in[22];
    const float* mb1 = (const float*)d_in[23];
    const float* mw2 = (const float*)d_in[24];
    const float* mb2 = (const float*)d_in[25];
    int E = in_sizes[1] / 2;

    float *h, *agg, *t1, *t2, *q, *k, *v, *o, *h1;
    cudaGetSymbolAddress((void**)&h,   g_h);
    cudaGetSymbolAddress((void**)&agg, g_agg);
    cudaGetSymbolAddress((void**)&t1,  g_t1);
    cudaGetSymbolAddress((void**)&t2,  g_t2);
    cudaGetSymbolAddress((void**)&q,   g_q);
    cudaGetSymbolAddress((void**)&k,   g_k);
    cudaGetSymbolAddress((void**)&v,   g_v);
    cudaGetSymbolAddress((void**)&o,   g_o);
    cudaGetSymbolAddress((void**)&h1,  g_h1);
    __half *wh, *wl;
    cudaGetSymbolAddress((void**)&wh, g_wh);
    cudaGetSymbolAddress((void**)&wl, g_wl);

    convw_all_kernel<<<(TOTW + 255)/256, 256>>>(gin_w1, gin_w2, wq, wk, wv, wo, mw1, mw2);

    dim3 gN256(CC/64,   NN/128);       // 4 x 32
    dim3 gN512(2*CC/64, NN/128);       // 8 x 32
    dim3 gqkv (CC/64,   NN/128, 3);
    int ewgrid = NN*CC/256;

    lin1_kernel<<<NN, CC>>>(x, lin1_w, lin1_b);

    for (int l = 0; l < LL; l++) {
        int w1 = l*CC*CC, w2 = l*2*CC*CC;
        // ---- GIN branch ----
        zero_kernel<<<ewgrid, 256>>>(agg, NN*CC);
        scatter_kernel<<<E/4, CC>>>(ei, E);
        gemm_mma_kernel<<<gN256, 128>>>(h, agg, wh + OFF_GW1 + w1, wl + OFF_GW1 + w1,
                                        gin_b1 + l*CC, t1, CC, CC, 1);
        gemm_mma_kernel<<<gN256, 128>>>(t1, nullptr, wh + OFF_GW2 + w1, wl + OFF_GW2 + w1,
                                        gin_b2 + l*CC, t2, CC, CC, 0);
        zero_stats_kernel<<<1, CC>>>();
        bn_stats_kernel<<<128, CC>>>(t2, h);
        bn_apply_kernel<<<ewgrid, 256>>>(t2, h, bn1_g + l*CC, bn1_b + l*CC, nullptr, h1);
        // ---- global attention ----
        qkv_mma_kernel<<<gqkv, 128>>>(h, wh, wl, bq + l*CC, bk + l*CC, bv + l*CC, q, k, v, l);
        flash_mma_kernel<<<dim3(NN/256, HH), 256>>>(q, k, v, o);
        gemm_mma_kernel<<<gN256, 128>>>(o, nullptr, wh + OFF_WO + w1, wl + OFF_WO + w1,
                                        bo + l*CC, t2, CC, CC, 0);
        zero_stats_kernel<<<1, CC>>>();
        bn_stats_kernel<<<128, CC>>>(t2, h);
        bn_apply_kernel<<<ewgrid, 256>>>(t2, h, bn2_g + l*CC, bn2_b + l*CC, h1, q);
        // ---- feedforward ----
        gemm_mma_kernel<<<gN512, 128>>>(q, nullptr, wh + OFF_MW1 + w2, wl + OFF_MW1 + w2,
                                        mb1 + l*2*CC, t1, 2*CC, CC, 1);
        gemm_mma_kernel<<<gN256, 128>>>(t1, nullptr, wh + OFF_MW2 + w2, wl + OFF_MW2 + w2,
                                        mb2 + l*CC, t2, CC, 2*CC, 0);
        zero_stats_kernel<<<1, CC>>>();
        bn_stats_kernel<<<128, CC>>>(t2, q);
        bn_apply_kernel<<<ewgrid, 256>>>(t2, q, bn3_g + l*CC, bn3_b + l*CC, nullptr,
                                         (l == LL-1) ? (float*)d_out : h);
    }
    (void)n_in; (void)out_size;
}